// round 3
// baseline (speedup 1.0000x reference)
#include <cuda_runtime.h>
#include <cuda_bf16.h>

// ---------------- Problem constants (fixed shapes) ----------------
#define NCTX   65536        // total context rows
#define BATCH  2048
#define EDIM   1024
#define HDIM   512
#define LDIM   512
#define LMAX   48

// ---------------- Scratch (static device globals; no allocation) ----------------
__device__ float g_bufA[NCTX * 512];
__device__ float g_bufB[NCTX * 512];
__device__ float g_bufC[NCTX * 512];
__device__ float g_bufD[NCTX * 512];
__device__ float g_seg [BATCH * 512];
__device__ float g_d1  [BATCH * 512];
__device__ float g_d2  [BATCH * 512];

// ---------------- GEMM: C[M,Ncols] = act( A @ W + bias ) ----------------
// A is logically [M,K] but may be a concat of two row-major blocks along K:
//   col k < K1  -> A1[m*K1 + k]          (leading dim K1)
//   col k >= K1 -> A2[m*(K-K1) + k-K1]   (leading dim K-K1)
// W is [K, Ncols] row-major. Requirements: M%128==0, Ncols%64==0, K%16==0, K1%16==0.
// ACT: 0=none, 1=leaky-relu(0.2), 2=clip[-1,1]
template <int ACT>
__global__ void __launch_bounds__(256)
gemm_bias_act(const float* __restrict__ A1, const float* __restrict__ A2,
              int K1, int K,
              const float* __restrict__ W, const float* __restrict__ bias,
              float* __restrict__ C, int M, int Ncols)
{
    const int BM = 128, BN = 64, BK = 16;
    __shared__ float As[BK][136];   // transposed: As[k][m], rows 16B aligned
    __shared__ float Bs[BK][68];    // Bs[k][n]

    const int tid = threadIdx.x;
    const int tx  = tid & 15;       // n direction (4 cols each)
    const int ty  = tid >> 4;       // m direction (8 rows each)

    const int m0 = blockIdx.y * BM;
    const int n0 = blockIdx.x * BN;
    const int K2 = K - K1;

    float acc[8][4];
#pragma unroll
    for (int i = 0; i < 8; i++)
#pragma unroll
        for (int j = 0; j < 4; j++) acc[i][j] = 0.f;

    for (int k0 = 0; k0 < K; k0 += BK) {
        // --- load A tile (128x16), 2 float4 per thread, coalesced ---
#pragma unroll
        for (int r = 0; r < 2; r++) {
            int t    = tid + r * 256;          // 0..511 float4 slots
            int arow = t >> 2;                 // 0..127
            int ak4  = (t & 3) * 4;            // 0,4,8,12
            int kg   = k0 + ak4;
            const float* Ap; int kk, ld;
            if (kg < K1) { Ap = A1; kk = kg;      ld = K1; }
            else         { Ap = A2; kk = kg - K1; ld = K2; }
            float4 v = *(const float4*)&Ap[(size_t)(m0 + arow) * ld + kk];
            As[ak4 + 0][arow] = v.x;
            As[ak4 + 1][arow] = v.y;
            As[ak4 + 2][arow] = v.z;
            As[ak4 + 3][arow] = v.w;
        }
        // --- load W tile (16x64), 1 float4 per thread ---
        {
            int brow = tid >> 4;               // 0..15
            int bc4  = (tid & 15) * 4;         // 0..60
            float4 v = *(const float4*)&W[(size_t)(k0 + brow) * Ncols + n0 + bc4];
            *(float4*)&Bs[brow][bc4] = v;
        }
        __syncthreads();

#pragma unroll
        for (int kk = 0; kk < BK; kk++) {
            float4 b4 = *(const float4*)&Bs[kk][tx * 4];
            float4 a0 = *(const float4*)&As[kk][ty * 8];
            float4 a1 = *(const float4*)&As[kk][ty * 8 + 4];
            float a[8] = {a0.x, a0.y, a0.z, a0.w, a1.x, a1.y, a1.z, a1.w};
            float b[4] = {b4.x, b4.y, b4.z, b4.w};
#pragma unroll
            for (int i = 0; i < 8; i++)
#pragma unroll
                for (int j = 0; j < 4; j++) acc[i][j] += a[i] * b[j];
        }
        __syncthreads();
    }

    // --- epilogue ---
    float4 bb = *(const float4*)&bias[n0 + tx * 4];
    float bv[4] = {bb.x, bb.y, bb.z, bb.w};
#pragma unroll
    for (int i = 0; i < 8; i++) {
        int row = m0 + ty * 8 + i;
        float4 o;
        float v0 = acc[i][0] + bv[0];
        float v1 = acc[i][1] + bv[1];
        float v2 = acc[i][2] + bv[2];
        float v3 = acc[i][3] + bv[3];
        if (ACT == 1) {
            v0 = v0 > 0.f ? v0 : 0.2f * v0;
            v1 = v1 > 0.f ? v1 : 0.2f * v1;
            v2 = v2 > 0.f ? v2 : 0.2f * v2;
            v3 = v3 > 0.f ? v3 : 0.2f * v3;
        } else if (ACT == 2) {
            v0 = fminf(fmaxf(v0, -1.f), 1.f);
            v1 = fminf(fmaxf(v1, -1.f), 1.f);
            v2 = fminf(fmaxf(v2, -1.f), 1.f);
            v3 = fminf(fmaxf(v3, -1.f), 1.f);
        }
        o.x = v0; o.y = v1; o.z = v2; o.w = v3;
        *(float4*)&C[(size_t)row * Ncols + n0 + tx * 4] = o;
    }
}

// ---------------- Attention per segment ----------------
// seg_out[b,d] = (1/len) * sum_m colsum[m] * v[m,d]
// colsum[m] = sum_{l<len} softmax_m(q_l . k_m / sqrt(LD))
__global__ void __launch_bounds__(256)
attn_kernel(const float* __restrict__ qN, const float* __restrict__ kN,
            const float* __restrict__ vN, const int* __restrict__ sse,
            float* __restrict__ seg_out)
{
    extern __shared__ float sm[];
    float* qs = sm;                 // LMAX*512
    float* ks = sm + LMAX * 512;    // LMAX*512
    __shared__ float scores[LMAX][LMAX];
    __shared__ float colsum[LMAX];

    const int b   = blockIdx.x;
    const int tid = threadIdx.x;
    const int start = sse[2 * b];          // int32 (JAX x64 disabled)
    const int end   = sse[2 * b + 1];
    const int len   = end - start;

    // stage q,k rows of this segment into smem (float4)
    {
        const float4* qg = (const float4*)(qN + (size_t)start * 512);
        const float4* kg = (const float4*)(kN + (size_t)start * 512);
        float4* q4 = (float4*)qs;
        float4* k4 = (float4*)ks;
        int tot = len * 128;
        for (int i = tid; i < tot; i += 256) { q4[i] = qg[i]; k4[i] = kg[i]; }
    }
    __syncthreads();

    // scores: warp per (l,m) dot product
    {
        const int warp = tid >> 5, lane = tid & 31;
        const float scale = 0.044194173824159216f;   // 1/sqrt(512)
        const float4* q4 = (const float4*)qs;
        const float4* k4 = (const float4*)ks;
        for (int p = warp; p < len * len; p += 8) {
            int l = p / len, m = p - l * len;
            const float4* qr = q4 + l * 128 + lane;
            const float4* kr = k4 + m * 128 + lane;
            float s = 0.f;
#pragma unroll
            for (int i = 0; i < 4; i++) {
                float4 a = qr[i * 32], c = kr[i * 32];
                s += a.x * c.x + a.y * c.y + a.z * c.z + a.w * c.w;
            }
#pragma unroll
            for (int off = 16; off > 0; off >>= 1)
                s += __shfl_xor_sync(0xffffffffu, s, off);
            if (lane == 0) scores[l][m] = s * scale;
        }
    }
    __syncthreads();

    // softmax per valid row (thread per row)
    if (tid < len) {
        float mx = -1e30f;
        for (int m = 0; m < len; m++) mx = fmaxf(mx, scores[tid][m]);
        float sum = 0.f;
        for (int m = 0; m < len; m++) {
            float e = __expf(scores[tid][m] - mx);
            scores[tid][m] = e; sum += e;
        }
        float inv = 1.f / sum;
        for (int m = 0; m < len; m++) scores[tid][m] *= inv;
    }
    __syncthreads();

    if (tid < len) {
        float cs = 0.f;
        for (int l = 0; l < len; l++) cs += scores[l][tid];
        colsum[tid] = cs;
    }
    __syncthreads();

    const float invlen = 1.f / (float)len;
    for (int d = tid; d < 512; d += 256) {
        float s = 0.f;
        for (int m = 0; m < len; m++)
            s += colsum[m] * vN[(size_t)(start + m) * 512 + d];
        seg_out[(size_t)b * 512 + d] = s * invlen;
    }
}

// ---------------- z = normalize(mean + exp(0.5*lv)*eps) * sqrt(LD) ----------------
__global__ void __launch_bounds__(256)
z_kernel(const float* __restrict__ mean, const float* __restrict__ lv,
         const float* __restrict__ eps, float* __restrict__ zout)
{
    __shared__ float red[256];
    const int b = blockIdx.x, tid = threadIdx.x;
    float zi[2];
    float ss = 0.f;
#pragma unroll
    for (int j = 0; j < 2; j++) {
        int d = tid + 256 * j;
        size_t idx = (size_t)b * 512 + d;
        float z = mean[idx] + __expf(0.5f * lv[idx]) * eps[idx];
        zi[j] = z; ss += z * z;
    }
    red[tid] = ss;
    __syncthreads();
    for (int s = 128; s > 0; s >>= 1) {
        if (tid < s) red[tid] += red[tid + s];
        __syncthreads();
    }
    float norm  = sqrtf(red[0]);
    float denom = fmaxf(norm, 1e-12f);
    float fac   = 22.627416997969522f / denom;   // sqrt(512)/denom
#pragma unroll
    for (int j = 0; j < 2; j++) {
        int d = tid + 256 * j;
        zout[(size_t)b * 512 + d] = zi[j] * fac;
    }
}

// ---------------- final head: out[m] = A[m,:]·w + b ----------------
__global__ void __launch_bounds__(256)
matvec_kernel(const float* __restrict__ A, const float* __restrict__ w,
              const float* __restrict__ b, float* __restrict__ out)
{
    const int lane = threadIdx.x;           // 32
    const int row  = blockIdx.x * 8 + threadIdx.y;
    float s = 0.f;
    for (int k = lane; k < 512; k += 32)
        s += A[(size_t)row * 512 + k] * w[k];
#pragma unroll
    for (int off = 16; off > 0; off >>= 1)
        s += __shfl_xor_sync(0xffffffffu, s, off);
    if (lane == 0) out[row] = s + b[0];
}

// ---------------- host side ----------------
extern "C" void kernel_launch(void* const* d_in, const int* in_sizes, int n_in,
                              void* d_out, int out_size)
{
    const float* tc   = (const float*)d_in[0];
    const float* tr   = (const float*)d_in[1];
    const float* cc   = (const float*)d_in[2];
    const float* cr   = (const float*)d_in[3];
    const float* eps  = (const float*)d_in[4];
    const float* pe_w1= (const float*)d_in[5];
    const float* pe_b1= (const float*)d_in[6];
    const float* pe_w2= (const float*)d_in[7];
    const float* pe_b2= (const float*)d_in[8];
    const float* pe_w3= (const float*)d_in[9];
    const float* pe_b3= (const float*)d_in[10];
    const float* wq   = (const float*)d_in[11];
    const float* bq   = (const float*)d_in[12];
    const float* wk   = (const float*)d_in[13];
    const float* bk   = (const float*)d_in[14];
    const float* wv   = (const float*)d_in[15];
    const float* bv   = (const float*)d_in[16];
    const float* wm   = (const float*)d_in[17];
    const float* bm   = (const float*)d_in[18];
    const float* wlv  = (const float*)d_in[19];
    const float* blv  = (const float*)d_in[20];
    const float* d_w1 = (const float*)d_in[21];
    const float* d_b1 = (const float*)d_in[22];
    const float* d_w2 = (const float*)d_in[23];
    const float* d_b2 = (const float*)d_in[24];
    const float* d_w3 = (const float*)d_in[25];
    const float* d_b3 = (const float*)d_in[26];
    const int*   sse  = (const int*)d_in[27];   // int32: JAX x64 is disabled
    // d_in[28] = user_type (unused by the reference computation)

    float* out = (float*)d_out;
    float* out_rc   = out;                       // [2048]
    float* out_rr   = out + BATCH;               // [2048]
    float* out_mean = out + 2 * BATCH;           // [2048*512]
    float* out_lv   = out_mean + BATCH * 512;    // [2048*512]
    float* out_z    = out_lv   + BATCH * 512;    // [2048*512]

    float *bufA, *bufB, *bufC, *bufD, *seg, *db1, *db2;
    cudaGetSymbolAddress((void**)&bufA, g_bufA);
    cudaGetSymbolAddress((void**)&bufB, g_bufB);
    cudaGetSymbolAddress((void**)&bufC, g_bufC);
    cudaGetSymbolAddress((void**)&bufD, g_bufD);
    cudaGetSymbolAddress((void**)&seg,  g_seg);
    cudaGetSymbolAddress((void**)&db1,  g_d1);
    cudaGetSymbolAddress((void**)&db2,  g_d2);

    dim3 blk(256);
    dim3 gN (512 / 64, NCTX  / 128);  // context-sized GEMMs
    dim3 gB (512 / 64, BATCH / 128);  // batch-sized GEMMs

    // pair-embed MLP
    gemm_bias_act<1><<<gN, blk>>>(cc, cr, EDIM, 2 * EDIM, pe_w1, pe_b1, bufA, NCTX, 512);
    gemm_bias_act<1><<<gN, blk>>>(bufA, bufA, 512, 512, pe_w2, pe_b2, bufB, NCTX, 512);
    gemm_bias_act<0><<<gN, blk>>>(bufB, bufB, 512, 512, pe_w3, pe_b3, bufA, NCTX, 512);

    // q,k,v projections over all context rows
    gemm_bias_act<0><<<gN, blk>>>(bufA, bufA, 512, 512, wq, bq, bufB, NCTX, 512);
    gemm_bias_act<0><<<gN, blk>>>(bufA, bufA, 512, 512, wk, bk, bufC, NCTX, 512);
    gemm_bias_act<0><<<gN, blk>>>(bufA, bufA, 512, 512, wv, bv, bufD, NCTX, 512);

    // per-segment attention -> seg_out
    const int attn_smem = LMAX * 512 * 2 * (int)sizeof(float);   // 192 KB dynamic
    cudaFuncSetAttribute(attn_kernel, cudaFuncAttributeMaxDynamicSharedMemorySize, attn_smem);
    attn_kernel<<<BATCH, 256, attn_smem>>>(bufB, bufC, bufD, sse, seg);

    // heads (clipped) written straight into the output tensor
    gemm_bias_act<2><<<gB, blk>>>(seg, seg, 512, 512, wm,  bm,  out_mean, BATCH, 512);
    gemm_bias_act<2><<<gB, blk>>>(seg, seg, 512, 512, wlv, blv, out_lv,   BATCH, 512);

    // reparameterize + normalize
    z_kernel<<<BATCH, 256>>>(out_mean, out_lv, eps, out_z);

    // decoder (chosen)
    gemm_bias_act<1><<<gB, blk>>>(tc, out_z, EDIM, EDIM + 512, d_w1, d_b1, db1, BATCH, 512);
    gemm_bias_act<1><<<gB, blk>>>(db1, db1, 512, 512, d_w2, d_b2, db2, BATCH, 512);
    matvec_kernel<<<BATCH / 8, dim3(32, 8)>>>(db2, d_w3, d_b3, out_rc);

    // decoder (rejected)
    gemm_bias_act<1><<<gB, blk>>>(tr, out_z, EDIM, EDIM + 512, d_w1, d_b1, db1, BATCH, 512);
    gemm_bias_act<1><<<gB, blk>>>(db1, db1, 512, 512, d_w2, d_b2, db2, BATCH, 512);
    matvec_kernel<<<BATCH / 8, dim3(32, 8)>>>(db2, d_w3, d_b3, out_rr);

    (void)in_sizes; (void)n_in; (void)out_size;
}

// round 5
// speedup vs baseline: 1.7955x; 1.7955x over previous
#include <cuda_runtime.h>
#include <cuda_bf16.h>
#include <cstdint>

// ---------------- Problem constants ----------------
#define NCTX   65536
#define BATCH  2048
#define LMAX   48

// ---------------- low-level helpers ----------------
__device__ __forceinline__ uint32_t smem_u32(const void* p) {
    uint32_t a;
    asm("{ .reg .u64 t; cvta.to.shared.u64 t, %1; cvt.u32.u64 %0, t; }" : "=r"(a) : "l"(p));
    return a;
}
__device__ __forceinline__ void cp16(uint32_t s, const void* g) {
    asm volatile("cp.async.cg.shared.global [%0], [%1], 16;" :: "r"(s), "l"(g));
}
__device__ __forceinline__ void cp_commit() {
    asm volatile("cp.async.commit_group;" ::: "memory");
}
__device__ __forceinline__ void cp_wait3() {
    asm volatile("cp.async.wait_group 3;" ::: "memory");
}
__device__ __forceinline__ void ldsm4(uint32_t& r0, uint32_t& r1, uint32_t& r2, uint32_t& r3,
                                      uint32_t addr) {
    asm volatile("ldmatrix.sync.aligned.m8n8.x4.shared.b16 {%0,%1,%2,%3}, [%4];"
                 : "=r"(r0), "=r"(r1), "=r"(r2), "=r"(r3) : "r"(addr));
}
__device__ __forceinline__ void mma16816(float* c, uint32_t a0, uint32_t a1, uint32_t a2,
                                         uint32_t a3, uint32_t b0, uint32_t b1) {
    asm volatile(
        "mma.sync.aligned.m16n8k16.row.col.f32.bf16.bf16.f32 "
        "{%0,%1,%2,%3}, {%4,%5,%6,%7}, {%8,%9}, {%0,%1,%2,%3};"
        : "+f"(c[0]), "+f"(c[1]), "+f"(c[2]), "+f"(c[3])
        : "r"(a0), "r"(a1), "r"(a2), "r"(a3), "r"(b0), "r"(b1));
}
__device__ __forceinline__ void hilo_split(float v, __nv_bfloat16& h, __nv_bfloat16& l) {
    h = __float2bfloat16_rn(v);
    l = __float2bfloat16_rn(v - __bfloat162float(h));
}

// ---------------- Scratch (static device globals) ----------------
__device__ __nv_bfloat16 g_cat0h[NCTX * 2048], g_cat0l[NCTX * 2048];
__device__ __nv_bfloat16 g_a1h[NCTX * 512],  g_a1l[NCTX * 512];
__device__ __nv_bfloat16 g_a2h[NCTX * 512],  g_a2l[NCTX * 512];
__device__ __nv_bfloat16 g_peh[NCTX * 512],  g_pel[NCTX * 512];
__device__ __nv_bfloat16 g_dcath[BATCH * 1536], g_dcatl[BATCH * 1536];
__device__ __nv_bfloat16 g_d1h[BATCH * 512], g_d1l[BATCH * 512];
__device__ __nv_bfloat16 g_segh[BATCH * 512], g_segl[BATCH * 512];
// transposed hi/lo weights: Wt[n][k]
__device__ __nv_bfloat16 g_w1th[512 * 2048], g_w1tl[512 * 2048];
__device__ __nv_bfloat16 g_w2th[512 * 512],  g_w2tl[512 * 512];
__device__ __nv_bfloat16 g_w3th[512 * 512],  g_w3tl[512 * 512];
__device__ __nv_bfloat16 g_wqth[512 * 512],  g_wqtl[512 * 512];
__device__ __nv_bfloat16 g_wkth[512 * 512],  g_wktl[512 * 512];
__device__ __nv_bfloat16 g_wvth[512 * 512],  g_wvtl[512 * 512];
__device__ __nv_bfloat16 g_wmth[512 * 512],  g_wmtl[512 * 512];
__device__ __nv_bfloat16 g_wlvth[512 * 512], g_wlvtl[512 * 512];
__device__ __nv_bfloat16 g_dw1th[512 * 1536], g_dw1tl[512 * 1536];
__device__ __nv_bfloat16 g_dw2th[512 * 512],  g_dw2tl[512 * 512];
// fp32 buffers
__device__ float g_q[NCTX * 512];
__device__ float g_k[NCTX * 512];
__device__ float g_v[NCTX * 512];
__device__ float g_seg[BATCH * 512];
__device__ float g_d2[BATCH * 512];

// ---------------- HMMA GEMM ----------------
// C[M,512] = act(A @ Wt^T + bias), A as hi/lo bf16 [M,K], Wt as hi/lo bf16 [512,K].
// 3-pass split: hi*hi + hi*lo + lo*hi, fp32 accum.
// CTA tile 128x128, BK=32, 4-stage cp.async pipeline.
// ACT: 0=none 1=lrelu 2=clip. OUTF32: 1 -> fp32 outF, 0 -> hi/lo bf16.
#define STG_BYTES 40960u     // 4 matrices * 128 rows * 80B
#define GEMM_DSM  (4 * 40960)

template <int ACT, int OUTF32>
__global__ void __launch_bounds__(256, 1)
gemm_mma(const __nv_bfloat16* __restrict__ Ahi, const __nv_bfloat16* __restrict__ Alo, int K,
         const __nv_bfloat16* __restrict__ Bhi, const __nv_bfloat16* __restrict__ Blo,
         const float* __restrict__ bias,
         float* __restrict__ outF, __nv_bfloat16* __restrict__ outHi, __nv_bfloat16* __restrict__ outLo)
{
    extern __shared__ char dsm[];
    const uint32_t smBase = smem_u32(dsm);

    const int tid = threadIdx.x;
    const int lane = tid & 31;
    const int w = tid >> 5;
    const int warp_m = w >> 2;     // 0..1
    const int warp_n = w & 3;      // 0..3
    const int m0 = blockIdx.y * 128;
    const int n0 = blockIdx.x * 128;

    float c[4][4][4];
#pragma unroll
    for (int mi = 0; mi < 4; mi++)
#pragma unroll
        for (int ni = 0; ni < 4; ni++)
#pragma unroll
            for (int r = 0; r < 4; r++) c[mi][ni][r] = 0.f;

    const int nk = K >> 5;   // K/32 stages

    // ---- stage loader: 2048 x 16B chunks (4 matrices x 128 rows x 4 chunks) ----
    auto load_stage = [&](int s) {
        const uint32_t sb = smBase + (uint32_t)(s & 3) * STG_BYTES;
        const int k0 = s << 5;
#pragma unroll
        for (int i = 0; i < 8; i++) {
            const int mat = i >> 1;                         // 0:Ah 1:Al 2:Bh 3:Bl
            const int r = ((tid + (i & 1) * 256) >> 2) & 127;
            const int k8 = tid & 3;
            const uint32_t dst = sb + (uint32_t)mat * 10240u + (uint32_t)r * 80u + (uint32_t)k8 * 16u;
            const __nv_bfloat16* src = (mat == 0) ? Ahi : (mat == 1) ? Alo : (mat == 2) ? Bhi : Blo;
            const int rowg = (mat < 2 ? m0 : n0) + r;
            cp16(dst, src + (size_t)rowg * K + k0 + k8 * 8);
        }
    };

    // prefetch 3 stages
    load_stage(0); cp_commit();
    load_stage(1); cp_commit();
    load_stage(2); cp_commit();

    const int lr = lane & 15;
    const uint32_t lc16 = (uint32_t)(lane >> 4) * 16u;

    for (int s = 0; s < nk; s++) {
        if (s + 3 < nk) load_stage(s + 3);
        cp_commit();                    // always commit (possibly empty) to keep count
        cp_wait3();
        __syncthreads();

        const uint32_t sb = smBase + (uint32_t)(s & 3) * STG_BYTES;
#pragma unroll
        for (int h = 0; h < 2; h++) {
            const uint32_t koff = (uint32_t)h * 32u + lc16;
            uint32_t ah[4][4], al[4][4], bh[2][4], bl[2][4];
#pragma unroll
            for (int mi = 0; mi < 4; mi++) {
                uint32_t addr = sb + (uint32_t)((warp_m * 64 + mi * 16 + lr) * 80) + koff;
                ldsm4(ah[mi][0], ah[mi][1], ah[mi][2], ah[mi][3], addr);
                ldsm4(al[mi][0], al[mi][1], al[mi][2], al[mi][3], addr + 10240u);
            }
#pragma unroll
            for (int bt = 0; bt < 2; bt++) {
                uint32_t addr = sb + 20480u + (uint32_t)((warp_n * 32 + bt * 16 + lr) * 80) + koff;
                ldsm4(bh[bt][0], bh[bt][1], bh[bt][2], bh[bt][3], addr);
                ldsm4(bl[bt][0], bl[bt][1], bl[bt][2], bl[bt][3], addr + 10240u);
            }
#pragma unroll
            for (int mi = 0; mi < 4; mi++)
#pragma unroll
                for (int ni = 0; ni < 4; ni++) {
                    const int bt = ni >> 1, sl = ni & 1;
                    const uint32_t b0h = bh[bt][sl], b1h = bh[bt][sl + 2];
                    const uint32_t b0l = bl[bt][sl], b1l = bl[bt][sl + 2];
                    mma16816(c[mi][ni], ah[mi][0], ah[mi][1], ah[mi][2], ah[mi][3], b0h, b1h);
                    mma16816(c[mi][ni], ah[mi][0], ah[mi][1], ah[mi][2], ah[mi][3], b0l, b1l);
                    mma16816(c[mi][ni], al[mi][0], al[mi][1], al[mi][2], al[mi][3], b0h, b1h);
                }
        }
        __syncthreads();
    }

    // ---- epilogue ----
#pragma unroll
    for (int mi = 0; mi < 4; mi++) {
        const int row = m0 + warp_m * 64 + mi * 16 + (lane >> 2);
#pragma unroll
        for (int ni = 0; ni < 4; ni++) {
            const int col = n0 + warp_n * 32 + ni * 8 + (lane & 3) * 2;
            const float b0 = bias[col], b1 = bias[col + 1];
            float v0 = c[mi][ni][0] + b0, v1 = c[mi][ni][1] + b1;
            float v2 = c[mi][ni][2] + b0, v3 = c[mi][ni][3] + b1;
            if (ACT == 1) {
                v0 = v0 > 0.f ? v0 : 0.2f * v0;
                v1 = v1 > 0.f ? v1 : 0.2f * v1;
                v2 = v2 > 0.f ? v2 : 0.2f * v2;
                v3 = v3 > 0.f ? v3 : 0.2f * v3;
            } else if (ACT == 2) {
                v0 = fminf(fmaxf(v0, -1.f), 1.f);
                v1 = fminf(fmaxf(v1, -1.f), 1.f);
                v2 = fminf(fmaxf(v2, -1.f), 1.f);
                v3 = fminf(fmaxf(v3, -1.f), 1.f);
            }
            if (OUTF32) {
                *(float2*)(outF + (size_t)row * 512 + col)       = make_float2(v0, v1);
                *(float2*)(outF + (size_t)(row + 8) * 512 + col) = make_float2(v2, v3);
            } else {
                __nv_bfloat16 h0, l0, h1, l1, h2, l2, h3, l3;
                hilo_split(v0, h0, l0); hilo_split(v1, h1, l1);
                hilo_split(v2, h2, l2); hilo_split(v3, h3, l3);
                *(__nv_bfloat162*)(outHi + (size_t)row * 512 + col)       = __nv_bfloat162(h0, h1);
                *(__nv_bfloat162*)(outLo + (size_t)row * 512 + col)       = __nv_bfloat162(l0, l1);
                *(__nv_bfloat162*)(outHi + (size_t)(row + 8) * 512 + col) = __nv_bfloat162(h2, h3);
                *(__nv_bfloat162*)(outLo + (size_t)(row + 8) * 512 + col) = __nv_bfloat162(l2, l3);
            }
        }
    }
}

// ---------------- fp32 -> hi/lo bf16 (strided into concat buffer) ----------------
__global__ void __launch_bounds__(256)
conv_hilo(const float* __restrict__ src, int total4, int kshift, int kmask,
          int dstStride, int dstOff,
          __nv_bfloat16* __restrict__ h, __nv_bfloat16* __restrict__ l)
{
    int i = blockIdx.x * 256 + threadIdx.x;
    if (i >= total4) return;
    int e = i << 2;
    int row = e >> kshift, col = e & kmask;
    float4 v = *(const float4*)(src + e);
    size_t o = (size_t)row * dstStride + dstOff + col;
    __nv_bfloat16 h0, l0, h1, l1, h2, l2, h3, l3;
    hilo_split(v.x, h0, l0); hilo_split(v.y, h1, l1);
    hilo_split(v.z, h2, l2); hilo_split(v.w, h3, l3);
    __nv_bfloat162* hp = (__nv_bfloat162*)(h + o);
    __nv_bfloat162* lp = (__nv_bfloat162*)(l + o);
    hp[0] = __nv_bfloat162(h0, h1); hp[1] = __nv_bfloat162(h2, h3);
    lp[0] = __nv_bfloat162(l0, l1); lp[1] = __nv_bfloat162(l2, l3);
}

// ---------------- weight transpose + hi/lo: W[K,512] -> Wt[512,K] ----------------
__global__ void __launch_bounds__(256)
wt_conv(const float* __restrict__ W, int K,
        __nv_bfloat16* __restrict__ Th, __nv_bfloat16* __restrict__ Tl)
{
    __shared__ float t[32][33];
    const int nb = blockIdx.x * 32, kb = blockIdx.y * 32;
    const int tx = threadIdx.x & 31, ty = threadIdx.x >> 5;  // 32 x 8
#pragma unroll
    for (int i = 0; i < 32; i += 8)
        t[ty + i][tx] = W[(size_t)(kb + ty + i) * 512 + nb + tx];
    __syncthreads();
#pragma unroll
    for (int i = 0; i < 32; i += 8) {
        float v = t[tx][ty + i];
        __nv_bfloat16 h, l;
        hilo_split(v, h, l);
        size_t o = (size_t)(nb + ty + i) * K + kb + tx;
        Th[o] = h; Tl[o] = l;
    }
}

// ---------------- Attention per segment ----------------
__global__ void __launch_bounds__(256)
attn_kernel(const float* __restrict__ qN, const float* __restrict__ kN,
            const float* __restrict__ vN, const int* __restrict__ sse,
            float* __restrict__ seg_out)
{
    extern __shared__ float sm[];
    float* qs = sm;
    float* ks = sm + LMAX * 512;
    __shared__ float scores[LMAX][LMAX];
    __shared__ float colsum[LMAX];

    const int b = blockIdx.x;
    const int tid = threadIdx.x;
    const int start = sse[2 * b];
    const int end = sse[2 * b + 1];
    const int len = end - start;

    {
        const float4* qg = (const float4*)(qN + (size_t)start * 512);
        const float4* kg = (const float4*)(kN + (size_t)start * 512);
        float4* q4 = (float4*)qs;
        float4* k4 = (float4*)ks;
        int tot = len * 128;
        for (int i = tid; i < tot; i += 256) { q4[i] = qg[i]; k4[i] = kg[i]; }
    }
    __syncthreads();

    {
        const int warp = tid >> 5, lane = tid & 31;
        const float scale = 0.044194173824159216f;
        const float4* q4 = (const float4*)qs;
        const float4* k4 = (const float4*)ks;
        for (int p = warp; p < len * len; p += 8) {
            int l = p / len, m = p - l * len;
            const float4* qr = q4 + l * 128 + lane;
            const float4* kr = k4 + m * 128 + lane;
            float s = 0.f;
#pragma unroll
            for (int i = 0; i < 4; i++) {
                float4 a = qr[i * 32], cc2 = kr[i * 32];
                s += a.x * cc2.x + a.y * cc2.y + a.z * cc2.z + a.w * cc2.w;
            }
#pragma unroll
            for (int off = 16; off > 0; off >>= 1)
                s += __shfl_xor_sync(0xffffffffu, s, off);
            if (lane == 0) scores[l][m] = s * scale;
        }
    }
    __syncthreads();

    if (tid < len) {
        float mx = -1e30f;
        for (int m = 0; m < len; m++) mx = fmaxf(mx, scores[tid][m]);
        float sum = 0.f;
        for (int m = 0; m < len; m++) {
            float e = __expf(scores[tid][m] - mx);
            scores[tid][m] = e; sum += e;
        }
        float inv = 1.f / sum;
        for (int m = 0; m < len; m++) scores[tid][m] *= inv;
    }
    __syncthreads();

    if (tid < len) {
        float cs = 0.f;
        for (int l = 0; l < len; l++) cs += scores[l][tid];
        colsum[tid] = cs;
    }
    __syncthreads();

    const float invlen = 1.f / (float)len;
    for (int d = tid; d < 512; d += 256) {
        float s = 0.f;
        for (int m = 0; m < len; m++)
            s += colsum[m] * vN[(size_t)(start + m) * 512 + d];
        seg_out[(size_t)b * 512 + d] = s * invlen;
    }
}

// ---------------- z = normalize(mean + exp(0.5*lv)*eps) * sqrt(512) ----------------
__global__ void __launch_bounds__(256)
z_kernel(const float* __restrict__ mean, const float* __restrict__ lv,
         const float* __restrict__ eps, float* __restrict__ zout)
{
    __shared__ float red[256];
    const int b = blockIdx.x, tid = threadIdx.x;
    float zi[2];
    float ss = 0.f;
#pragma unroll
    for (int j = 0; j < 2; j++) {
        int d = tid + 256 * j;
        size_t idx = (size_t)b * 512 + d;
        float z = mean[idx] + __expf(0.5f * lv[idx]) * eps[idx];
        zi[j] = z; ss += z * z;
    }
    red[tid] = ss;
    __syncthreads();
    for (int s = 128; s > 0; s >>= 1) {
        if (tid < s) red[tid] += red[tid + s];
        __syncthreads();
    }
    float denom = fmaxf(sqrtf(red[0]), 1e-12f);
    float fac = 22.627416997969522f / denom;
#pragma unroll
    for (int j = 0; j < 2; j++) {
        int d = tid + 256 * j;
        zout[(size_t)b * 512 + d] = zi[j] * fac;
    }
}

// ---------------- final head matvec ----------------
__global__ void __launch_bounds__(256)
matvec_kernel(const float* __restrict__ A, const float* __restrict__ w,
              const float* __restrict__ b, float* __restrict__ out)
{
    const int lane = threadIdx.x;
    const int row = blockIdx.x * 8 + threadIdx.y;
    float s = 0.f;
    for (int k = lane; k < 512; k += 32)
        s += A[(size_t)row * 512 + k] * w[k];
#pragma unroll
    for (int off = 16; off > 0; off >>= 1)
        s += __shfl_xor_sync(0xffffffffu, s, off);
    if (lane == 0) out[row] = s + b[0];
}

// ---------------- host side ----------------
extern "C" void kernel_launch(void* const* d_in, const int* in_sizes, int n_in,
                              void* d_out, int out_size)
{
    const float* tc    = (const float*)d_in[0];
    const float* tr    = (const float*)d_in[1];
    const float* cc    = (const float*)d_in[2];
    const float* cr    = (const float*)d_in[3];
    const float* eps   = (const float*)d_in[4];
    const float* pe_w1 = (const float*)d_in[5];
    const float* pe_b1 = (const float*)d_in[6];
    const float* pe_w2 = (const float*)d_in[7];
    const float* pe_b2 = (const float*)d_in[8];
    const float* pe_w3 = (const float*)d_in[9];
    const float* pe_b3 = (const float*)d_in[10];
    const float* wq    = (const float*)d_in[11];
    const float* bq    = (const float*)d_in[12];
    const float* wk    = (const float*)d_in[13];
    const float* bk    = (const float*)d_in[14];
    const float* wv    = (const float*)d_in[15];
    const float* bv    = (const float*)d_in[16];
    const float* wm    = (const float*)d_in[17];
    const float* bm    = (const float*)d_in[18];
    const float* wlv   = (const float*)d_in[19];
    const float* blv   = (const float*)d_in[20];
    const float* d_w1  = (const float*)d_in[21];
    const float* d_b1  = (const float*)d_in[22];
    const float* d_w2  = (const float*)d_in[23];
    const float* d_b2  = (const float*)d_in[24];
    const float* d_w3  = (const float*)d_in[25];
    const float* d_b3  = (const float*)d_in[26];
    const int*   sse   = (const int*)d_in[27];

    float* out = (float*)d_out;
    float* out_rc   = out;
    float* out_rr   = out + BATCH;
    float* out_mean = out + 2 * BATCH;
    float* out_lv   = out_mean + BATCH * 512;
    float* out_z    = out_lv + BATCH * 512;

    __nv_bfloat16 *cat0h, *cat0l, *a1h, *a1l, *a2h, *a2l, *peh, *pel;
    __nv_bfloat16 *dcath, *dcatl, *d1h, *d1l, *segh, *segl;
    __nv_bfloat16 *w1th, *w1tl, *w2th, *w2tl, *w3th, *w3tl;
    __nv_bfloat16 *wqth, *wqtl, *wkth, *wktl, *wvth, *wvtl;
    __nv_bfloat16 *wmth, *wmtl, *wlvth, *wlvtl;
    __nv_bfloat16 *dw1th, *dw1tl, *dw2th, *dw2tl;
    float *qf, *kf, *vf, *seg, *d2f;
    cudaGetSymbolAddress((void**)&cat0h, g_cat0h); cudaGetSymbolAddress((void**)&cat0l, g_cat0l);
    cudaGetSymbolAddress((void**)&a1h, g_a1h);     cudaGetSymbolAddress((void**)&a1l, g_a1l);
    cudaGetSymbolAddress((void**)&a2h, g_a2h);     cudaGetSymbolAddress((void**)&a2l, g_a2l);
    cudaGetSymbolAddress((void**)&peh, g_peh);     cudaGetSymbolAddress((void**)&pel, g_pel);
    cudaGetSymbolAddress((void**)&dcath, g_dcath); cudaGetSymbolAddress((void**)&dcatl, g_dcatl);
    cudaGetSymbolAddress((void**)&d1h, g_d1h);     cudaGetSymbolAddress((void**)&d1l, g_d1l);
    cudaGetSymbolAddress((void**)&segh, g_segh);   cudaGetSymbolAddress((void**)&segl, g_segl);
    cudaGetSymbolAddress((void**)&w1th, g_w1th);   cudaGetSymbolAddress((void**)&w1tl, g_w1tl);
    cudaGetSymbolAddress((void**)&w2th, g_w2th);   cudaGetSymbolAddress((void**)&w2tl, g_w2tl);
    cudaGetSymbolAddress((void**)&w3th, g_w3th);   cudaGetSymbolAddress((void**)&w3tl, g_w3tl);
    cudaGetSymbolAddress((void**)&wqth, g_wqth);   cudaGetSymbolAddress((void**)&wqtl, g_wqtl);
    cudaGetSymbolAddress((void**)&wkth, g_wkth);   cudaGetSymbolAddress((void**)&wktl, g_wktl);
    cudaGetSymbolAddress((void**)&wvth, g_wvth);   cudaGetSymbolAddress((void**)&wvtl, g_wvtl);
    cudaGetSymbolAddress((void**)&wmth, g_wmth);   cudaGetSymbolAddress((void**)&wmtl, g_wmtl);
    cudaGetSymbolAddress((void**)&wlvth, g_wlvth); cudaGetSymbolAddress((void**)&wlvtl, g_wlvtl);
    cudaGetSymbolAddress((void**)&dw1th, g_dw1th); cudaGetSymbolAddress((void**)&dw1tl, g_dw1tl);
    cudaGetSymbolAddress((void**)&dw2th, g_dw2th); cudaGetSymbolAddress((void**)&dw2tl, g_dw2tl);
    cudaGetSymbolAddress((void**)&qf, g_q);
    cudaGetSymbolAddress((void**)&kf, g_k);
    cudaGetSymbolAddress((void**)&vf, g_v);
    cudaGetSymbolAddress((void**)&seg, g_seg);
    cudaGetSymbolAddress((void**)&d2f, g_d2);

    cudaFuncSetAttribute(gemm_mma<0, 0>, cudaFuncAttributeMaxDynamicSharedMemorySize, GEMM_DSM);
    cudaFuncSetAttribute(gemm_mma<0, 1>, cudaFuncAttributeMaxDynamicSharedMemorySize, GEMM_DSM);
    cudaFuncSetAttribute(gemm_mma<1, 0>, cudaFuncAttributeMaxDynamicSharedMemorySize, GEMM_DSM);
    cudaFuncSetAttribute(gemm_mma<1, 1>, cudaFuncAttributeMaxDynamicSharedMemorySize, GEMM_DSM);
    cudaFuncSetAttribute(gemm_mma<2, 1>, cudaFuncAttributeMaxDynamicSharedMemorySize, GEMM_DSM);
    const int attn_smem = LMAX * 512 * 2 * (int)sizeof(float);
    cudaFuncSetAttribute(attn_kernel, cudaFuncAttributeMaxDynamicSharedMemorySize, attn_smem);

    // ---- weight transposes + hi/lo splits ----
    wt_conv<<<dim3(16, 64), 256>>>(pe_w1, 2048, w1th, w1tl);
    wt_conv<<<dim3(16, 16), 256>>>(pe_w2, 512, w2th, w2tl);
    wt_conv<<<dim3(16, 16), 256>>>(pe_w3, 512, w3th, w3tl);
    wt_conv<<<dim3(16, 16), 256>>>(wq, 512, wqth, wqtl);
    wt_conv<<<dim3(16, 16), 256>>>(wk, 512, wkth, wktl);
    wt_conv<<<dim3(16, 16), 256>>>(wv, 512, wvth, wvtl);
    wt_conv<<<dim3(16, 16), 256>>>(wm, 512, wmth, wmtl);
    wt_conv<<<dim3(16, 16), 256>>>(wlv, 512, wlvth, wlvtl);
    wt_conv<<<dim3(16, 48), 256>>>(d_w1, 1536, dw1th, dw1tl);
    wt_conv<<<dim3(16, 16), 256>>>(d_w2, 512, dw2th, dw2tl);

    // ---- input conversion: concat(cc, cr) -> cat0 hi/lo [NCTX, 2048] ----
    conv_hilo<<<NCTX * 1024 / 4 / 256, 256>>>(cc, NCTX * 1024 / 4, 10, 1023, 2048, 0, cat0h, cat0l);
    conv_hilo<<<NCTX * 1024 / 4 / 256, 256>>>(cr, NCTX * 1024 / 4, 10, 1023, 2048, 1024, cat0h, cat0l);

    dim3 gN(4, NCTX / 128);
    dim3 gB(4, BATCH / 128);

    // pair-embed MLP
    gemm_mma<1, 0><<<gN, 256, GEMM_DSM>>>(cat0h, cat0l, 2048, w1th, w1tl, pe_b1, nullptr, a1h, a1l);
    gemm_mma<1, 0><<<gN, 256, GEMM_DSM>>>(a1h, a1l, 512, w2th, w2tl, pe_b2, nullptr, a2h, a2l);
    gemm_mma<0, 0><<<gN, 256, GEMM_DSM>>>(a2h, a2l, 512, w3th, w3tl, pe_b3, nullptr, peh, pel);

    // q,k,v projections (fp32 out)
    gemm_mma<0, 1><<<gN, 256, GEMM_DSM>>>(peh, pel, 512, wqth, wqtl, bq, qf, nullptr, nullptr);
    gemm_mma<0, 1><<<gN, 256, GEMM_DSM>>>(peh, pel, 512, wkth, wktl, bk, kf, nullptr, nullptr);
    gemm_mma<0, 1><<<gN, 256, GEMM_DSM>>>(peh, pel, 512, wvth, wvtl, bv, vf, nullptr, nullptr);

    // attention
    attn_kernel<<<BATCH, 256, attn_smem>>>(qf, kf, vf, sse, seg);

    // heads (clip) via HMMA
    conv_hilo<<<BATCH * 512 / 4 / 256, 256>>>(seg, BATCH * 512 / 4, 9, 511, 512, 0, segh, segl);
    gemm_mma<2, 1><<<gB, 256, GEMM_DSM>>>(segh, segl, 512, wmth, wmtl, bm, out_mean, nullptr, nullptr);
    gemm_mma<2, 1><<<gB, 256, GEMM_DSM>>>(segh, segl, 512, wlvth, wlvtl, blv, out_lv, nullptr, nullptr);

    // z
    z_kernel<<<BATCH, 256>>>(out_mean, out_lv, eps, out_z);

    // decoder concat z part (cols 1024..1535, shared by both passes)
    conv_hilo<<<BATCH * 512 / 4 / 256, 256>>>(out_z, BATCH * 512 / 4, 9, 511, 1536, 1024, dcath, dcatl);

    // decoder (chosen)
    conv_hilo<<<BATCH * 1024 / 4 / 256, 256>>>(tc, BATCH * 1024 / 4, 10, 1023, 1536, 0, dcath, dcatl);
    gemm_mma<1, 0><<<gB, 256, GEMM_DSM>>>(dcath, dcatl, 1536, dw1th, dw1tl, d_b1, nullptr, d1h, d1l);
    gemm_mma<1, 1><<<gB, 256, GEMM_DSM>>>(d1h, d1l, 512, dw2th, dw2tl, d_b2, d2f, nullptr, nullptr);
    matvec_kernel<<<BATCH / 8, dim3(32, 8)>>>(d2f, d_w3, d_b3, out_rc);

    // decoder (rejected)
    conv_hilo<<<BATCH * 1024 / 4 / 256, 256>>>(tr, BATCH * 1024 / 4, 10, 1023, 1536, 0, dcath, dcatl);
    gemm_mma<1, 0><<<gB, 256, GEMM_DSM>>>(dcath, dcatl, 1536, dw1th, dw1tl, d_b1, nullptr, d1h, d1l);
    gemm_mma<1, 1><<<gB, 256, GEMM_DSM>>>(d1h, d1l, 512, dw2th, dw2tl, d_b2, d2f, nullptr, nullptr);
    matvec_kernel<<<BATCH / 8, dim3(32, 8)>>>(d2f, d_w3, d_b3, out_rr);

    (void)in_sizes; (void)n_in; (void)out_size;
}